// round 6
// baseline (speedup 1.0000x reference)
#include <cuda_runtime.h>
#include <cuda_fp16.h>
#include <cstdint>

// ---------------- fixed problem sizes ----------------
#define B_   4
#define T_   2048
#define S_   4096
#define KD   512
#define MQ_  (B_*T_)    // 8192
#define MK_  (B_*S_)    // 16384

// ---------------- GEMM tiling ----------------
#define BM 128
#define BN 128
#define BK 64
#define STAGE_BYTES (BM*128 + BN*128)       // 32 KB
#define SMEM_MAIN   (2*STAGE_BYTES)         // 64 KB
#define SMEM_EXTRA  640
#define SMEM_ALL    (SMEM_MAIN + SMEM_EXTRA)

#define MSPLIT 4

// ---------------- scratch ----------------
__device__ __half g_xq16[MQ_ * KD];
__device__ __half g_xk16[MK_ * KD];
__device__ __half g_wqT[KD * KD];
__device__ __half g_wkT[KD * KD];
__device__ float  g_Mf[MSPLIT * KD * KD];
__device__ __half g_M  [KD * KD];
__device__ __half g_Y  [MQ_ * KD];
__device__ float  g_u  [MQ_];
__device__ float  g_v  [MK_];
__device__ float  g_wu [KD];
__device__ float  g_wv [KD];
__device__ float  g_c;

// ---------------- helpers ----------------
#define SWZ(o) ((o) ^ (((o) >> 3) & 0x70))

__device__ __forceinline__ uint32_t smem_u32(const void* p) {
    uint32_t a;
    asm("{ .reg .u64 t; cvta.to.shared.u64 t, %1; cvt.u32.u64 %0, t; }"
        : "=r"(a) : "l"(p));
    return a;
}

__device__ __forceinline__ void cp16(uint32_t s, const void* g) {
    asm volatile("cp.async.cg.shared.global [%0], [%1], 16;" :: "r"(s), "l"(g));
}
#define CP_COMMIT() asm volatile("cp.async.commit_group;" ::: "memory")
#define CP_WAIT0()  asm volatile("cp.async.wait_group 0;" ::: "memory")
#define CP_WAIT1()  asm volatile("cp.async.wait_group 1;" ::: "memory")

__device__ __forceinline__ void ldsm4(uint32_t* r, uint32_t addr) {
    asm volatile("ldmatrix.sync.aligned.m8n8.x4.shared.b16 {%0,%1,%2,%3}, [%4];"
                 : "=r"(r[0]), "=r"(r[1]), "=r"(r[2]), "=r"(r[3]) : "r"(addr));
}

__device__ __forceinline__ void mma16816(float* c, const uint32_t* a,
                                         uint32_t b0, uint32_t b1) {
    asm volatile(
        "mma.sync.aligned.m16n8k16.row.col.f32.f16.f16.f32 "
        "{%0,%1,%2,%3}, {%4,%5,%6,%7}, {%8,%9}, {%0,%1,%2,%3};"
        : "+f"(c[0]), "+f"(c[1]), "+f"(c[2]), "+f"(c[3])
        : "r"(a[0]), "r"(a[1]), "r"(a[2]), "r"(a[3]), "r"(b0), "r"(b1));
}

// fp16-accumulate variant (probe): D/C are 2 b32 regs (4 halves)
__device__ __forceinline__ void mma16816h(uint32_t* d, const uint32_t* a,
                                          uint32_t b0, uint32_t b1) {
    asm volatile(
        "mma.sync.aligned.m16n8k16.row.col.f16.f16.f16.f16 "
        "{%0,%1}, {%2,%3,%4,%5}, {%6,%7}, {%0,%1};"
        : "+r"(d[0]), "+r"(d[1])
        : "r"(a[0]), "r"(a[1]), "r"(a[2]), "r"(a[3]), "r"(b0), "r"(b1));
}

// ---------------- prep: weight transpose+cvt, wu, wv, c ----------------
__global__ void prep_small(const float* __restrict__ Wq, const float* __restrict__ Wk,
                           const float* __restrict__ bq, const float* __restrict__ bk) {
    const int b = blockIdx.x;
    if (b < 512) {
        __shared__ float tile[32][33];
        const int w = b >> 8;
        const int t = b & 255;
        const float* src = w ? Wk : Wq;
        __half* dst = w ? g_wkT : g_wqT;
        const int d0 = (t & 15) * 32, j0 = (t >> 4) * 32;
        const int tx = threadIdx.x & 31, ty = threadIdx.x >> 5;
#pragma unroll
        for (int i = 0; i < 4; ++i) {
            int j = ty + i * 8;
            tile[j][tx] = src[(size_t)(j0 + j) * KD + d0 + tx];
        }
        __syncthreads();
#pragma unroll
        for (int i = 0; i < 4; ++i) {
            int d = ty + i * 8;
            dst[(size_t)(d0 + d) * KD + j0 + tx] = __float2half(tile[tx][d]);
        }
    } else if (b < 516) {
        const int which = b - 512;
        const int d = (which & 1) * 256 + threadIdx.x;
        const float* W = (which < 2) ? Wq : Wk;
        const float* bb = (which < 2) ? bk : bq;
        float* dst = (which < 2) ? g_wu : g_wv;
        float s = 0.f;
#pragma unroll 8
        for (int j = 0; j < KD; ++j) s += bb[j] * W[(size_t)j * KD + d];
        dst[d] = s;
    } else {
        __shared__ float red[256];
        float s = bq[threadIdx.x] * bk[threadIdx.x] +
                  bq[threadIdx.x + 256] * bk[threadIdx.x + 256];
        red[threadIdx.x] = s;
        __syncthreads();
        for (int o = 128; o; o >>= 1) {
            if (threadIdx.x < (unsigned)o) red[threadIdx.x] += red[threadIdx.x + o];
            __syncthreads();
        }
        if (threadIdx.x == 0) g_c = red[0];
    }
}

// ---------------- fused fp32->fp16 convert + row GEMV (u, v) ----------------
__global__ void conv_gemv(const float4* __restrict__ xq, const float4* __restrict__ xk) {
    const int gw = (blockIdx.x * blockDim.x + threadIdx.x) >> 5;
    const int l = threadIdx.x & 31;
    const bool isQ = gw < MQ_;
    const int r = isQ ? gw : gw - MQ_;
    const float4* src = isQ ? xq : xk;
    const float4* w4 = (const float4*)(isQ ? g_wu : g_wv);
    __half2* dst = (__half2*)(isQ ? g_xq16 : g_xk16);
    float dot = 0.f;
#pragma unroll
    for (int i = 0; i < 4; ++i) {
        const int idx = r * (KD / 4) + l + i * 32;
        float4 a = src[idx];
        float4 w = w4[l + i * 32];
        dst[idx * 2 + 0] = __floats2half2_rn(a.x, a.y);
        dst[idx * 2 + 1] = __floats2half2_rn(a.z, a.w);
        dot += a.x * w.x + a.y * w.y + a.z * w.z + a.w * w.w;
    }
#pragma unroll
    for (int o = 16; o; o >>= 1) dot += __shfl_xor_sync(0xffffffff, dot, o);
    if (l == 0) {
        if (isQ) g_u[r] = (dot + g_c) * 0.015625f;
        else     g_v[r] = dot * 0.015625f;
    }
}

// ---------------- sum split-K partials of M, convert to fp16 ----------------
__global__ void m_cvt() {
    const int i = blockIdx.x * blockDim.x + threadIdx.x;   // over KD*KD/4
    float4 s = *(const float4*)(g_Mf + (size_t)i * 4);
#pragma unroll
    for (int z = 1; z < MSPLIT; ++z) {
        float4 p = *(const float4*)(g_Mf + (size_t)z * (KD * KD) + (size_t)i * 4);
        s.x += p.x; s.y += p.y; s.z += p.z; s.w += p.w;
    }
    __half2* d = (__half2*)(g_M + (size_t)i * 4);
    d[0] = __floats2half2_rn(s.x, s.y);
    d[1] = __floats2half2_rn(s.z, s.w);
}

// ---------------- fp16 GEMM:  D[m,n] = sum_k A[m,k] * B[n,k]  ----------------
// MODE 0: outH = D * scale (fp16), fp32 accum
// MODE 1: outF = D + u[row] + v[col], mask -> -inf, fp32, streaming stores
// MODE 2: split-K slice -> fp32 partials
// MODE 3: outH = D * scale (fp16), fp16 accum chained per k64 chunk (probe)
template <int MODE>
__global__ __launch_bounds__(256, 2) void hgemm(
    const __half* __restrict__ A, const __half* __restrict__ Bm,
    __half* __restrict__ outH, float* __restrict__ outF,
    float* __restrict__ outMf, const unsigned char* __restrict__ mask,
    float scale, int aRows, int bRows, int outLd, int nch) {
    extern __shared__ char smem[];
    const uint32_t sb = smem_u32(smem);
    const int tid = threadIdx.x;
    const int wid = tid >> 5;
    const int l = tid & 31;
    const int wm = wid >> 2;
    const int wn = wid & 3;
    const int mt = blockIdx.x, nt = blockIdx.y, bz = blockIdx.z;

    size_t aBase, bBase;
    int kStart;
    if (MODE == 2) {
        aBase = (size_t)mt * BM * KD;
        bBase = (size_t)nt * BN * KD;
        kStart = bz * (KD / MSPLIT);
    } else {
        aBase = ((size_t)bz * aRows + (size_t)mt * BM) * KD;
        bBase = ((size_t)bz * bRows + (size_t)nt * BN) * KD;
        kStart = 0;
    }

    float* sv = (float*)(smem + SMEM_MAIN);
    unsigned char* sm = (unsigned char*)(smem + SMEM_MAIN + 512);
    if (MODE == 1 && tid < 128) {
        const size_t colg = (size_t)bz * S_ + (size_t)nt * BN + tid;
        sv[tid] = g_v[colg];
        sm[tid] = mask[colg];
    }

    float acc[4][4][4];
#pragma unroll
    for (int i = 0; i < 4; ++i)
#pragma unroll
        for (int j = 0; j < 4; ++j)
#pragma unroll
            for (int c = 0; c < 4; ++c) acc[i][j][c] = 0.f;

    const int aRow = wm * 64 + (l & 15);
    const int aKsel = ((l >> 4) & 1) * 16;
    const int bRow = wn * 32 + (l & 7) + ((l >> 4) & 1) * 8;
    const int bKsel = ((l >> 3) & 1) * 16;

    auto load_tile = [&](int stg, int k0) {
        const uint32_t sA = sb + stg * STAGE_BYTES;
        const uint32_t sB = sA + BM * 128;
#pragma unroll
        for (int t = 0; t < 4; ++t) {
            int i = tid + t * 256;
            int r = i >> 3, c = i & 7;
            cp16(sA + SWZ((uint32_t)(r * 128 + c * 16)),
                 A + aBase + (size_t)r * KD + k0 + c * 8);
        }
#pragma unroll
        for (int t = 0; t < 4; ++t) {
            int i = tid + t * 256;
            int r = i >> 3, c = i & 7;
            cp16(sB + SWZ((uint32_t)(r * 128 + c * 16)),
                 Bm + bBase + (size_t)r * KD + k0 + c * 8);
        }
    };

    load_tile(0, kStart);
    CP_COMMIT();

    int stg = 0;
    for (int ch = 0; ch < nch; ++ch) {
        if (ch + 1 < nch) {
            load_tile(stg ^ 1, kStart + (ch + 1) * BK);
            CP_COMMIT();
            CP_WAIT1();
        } else {
            CP_WAIT0();
        }
        __syncthreads();

        const uint32_t sA = sb + stg * STAGE_BYTES;
        const uint32_t sB = sA + BM * 128;

        uint32_t dh[4][4][2];
        if (MODE == 3) {
#pragma unroll
            for (int mi = 0; mi < 4; ++mi)
#pragma unroll
                for (int ni = 0; ni < 4; ++ni)
                    dh[mi][ni][0] = dh[mi][ni][1] = 0u;
        }

#pragma unroll
        for (int ks = 0; ks < BK / 16; ++ks) {
            uint32_t afr[4][4];
            uint32_t bfr[2][4];
#pragma unroll
            for (int mi = 0; mi < 4; ++mi)
                ldsm4(afr[mi], sA + SWZ((uint32_t)((aRow + mi * 16) * 128 +
                                                   ks * 32 + aKsel)));
#pragma unroll
            for (int nb = 0; nb < 2; ++nb)
                ldsm4(bfr[nb], sB + SWZ((uint32_t)((bRow + nb * 16) * 128 +
                                                   ks * 32 + bKsel)));
#pragma unroll
            for (int mi = 0; mi < 4; ++mi)
#pragma unroll
                for (int ni = 0; ni < 4; ++ni) {
                    if (MODE == 3)
                        mma16816h(dh[mi][ni], afr[mi],
                                  bfr[ni >> 1][(ni & 1) * 2],
                                  bfr[ni >> 1][(ni & 1) * 2 + 1]);
                    else
                        mma16816(acc[mi][ni], afr[mi],
                                 bfr[ni >> 1][(ni & 1) * 2],
                                 bfr[ni >> 1][(ni & 1) * 2 + 1]);
                }
        }

        if (MODE == 3) {
            // unpack fp16 chunk-accumulators into fp32
#pragma unroll
            for (int mi = 0; mi < 4; ++mi)
#pragma unroll
                for (int ni = 0; ni < 4; ++ni) {
                    float2 f0 = __half22float2(*(__half2*)&dh[mi][ni][0]);
                    float2 f1 = __half22float2(*(__half2*)&dh[mi][ni][1]);
                    acc[mi][ni][0] += f0.x;
                    acc[mi][ni][1] += f0.y;
                    acc[mi][ni][2] += f1.x;
                    acc[mi][ni][3] += f1.y;
                }
        }
        __syncthreads();
        stg ^= 1;
    }

    // ---------------- epilogue ----------------
    const int gid = l >> 2, tig = l & 3;
#pragma unroll
    for (int mi = 0; mi < 4; ++mi) {
#pragma unroll
        for (int h = 0; h < 2; ++h) {
            const int row = mt * BM + wm * 64 + mi * 16 + gid + h * 8;
            const size_t rowg =
                (MODE == 2) ? (size_t)row : (size_t)bz * aRows + row;
            float uu = 0.f;
            if (MODE == 1) uu = g_u[rowg];
#pragma unroll
            for (int ni = 0; ni < 4; ++ni) {
                const int lcol = wn * 32 + ni * 8 + tig * 2;
                const int col = nt * BN + lcol;
                const float v0 = acc[mi][ni][h * 2 + 0];
                const float v1 = acc[mi][ni][h * 2 + 1];
                if (MODE == 0 || MODE == 3) {
                    *(__half2*)(outH + rowg * outLd + col) =
                        __floats2half2_rn(v0 * scale, v1 * scale);
                } else if (MODE == 2) {
                    float* dst = outMf + (size_t)bz * (KD * KD) +
                                 rowg * outLd + col;
                    dst[0] = v0;
                    dst[1] = v1;
                } else {
                    const float NEG_INF = __int_as_float(0xff800000);
                    float2 o;
                    o.x = sm[lcol + 0] ? NEG_INF : v0 + uu + sv[lcol + 0];
                    o.y = sm[lcol + 1] ? NEG_INF : v1 + uu + sv[lcol + 1];
                    __stcs((float2*)(outF + rowg * (size_t)S_ + col), o);
                }
            }
        }
    }
}

// ---------------- host launch ----------------
extern "C" void kernel_launch(void* const* d_in, const int* in_sizes, int n_in,
                              void* d_out, int out_size) {
    const float* query = (const float*)d_in[0];
    const float* keys = (const float*)d_in[1];
    const unsigned char* mask = (const unsigned char*)d_in[2];
    const float* q_w = (const float*)d_in[3];
    const float* q_b = (const float*)d_in[4];
    const float* k_w = (const float*)d_in[5];
    const float* k_b = (const float*)d_in[6];

    void *xq16, *xk16, *wqT, *wkT, *Mf, *M, *Y;
    cudaGetSymbolAddress(&xq16, g_xq16);
    cudaGetSymbolAddress(&xk16, g_xk16);
    cudaGetSymbolAddress(&wqT, g_wqT);
    cudaGetSymbolAddress(&wkT, g_wkT);
    cudaGetSymbolAddress(&Mf, g_Mf);
    cudaGetSymbolAddress(&M, g_M);
    cudaGetSymbolAddress(&Y, g_Y);

    cudaFuncSetAttribute(hgemm<1>, cudaFuncAttributeMaxDynamicSharedMemorySize,
                         SMEM_ALL);
    cudaFuncSetAttribute(hgemm<2>, cudaFuncAttributeMaxDynamicSharedMemorySize,
                         SMEM_ALL);
    cudaFuncSetAttribute(hgemm<3>, cudaFuncAttributeMaxDynamicSharedMemorySize,
                         SMEM_ALL);

    // 1) weight transpose/convert + wu, wv, c
    prep_small<<<517, 256>>>(q_w, k_w, q_b, k_b);

    // 2) convert xq/xk to fp16 + per-row GEMVs u, v
    conv_gemv<<<(MQ_ + MK_) / 8, 256>>>((const float4*)query, (const float4*)keys);

    // 3) M partials: split-K over 4 slices (K=128 each)
    hgemm<2><<<dim3(KD / BM, KD / BN, MSPLIT), 256, SMEM_ALL>>>(
        (const __half*)wkT, (const __half*)wqT, nullptr, nullptr, (float*)Mf,
        nullptr, 1.0f, KD, KD, KD, (KD / MSPLIT) / BK);

    // 4) reduce partials -> fp16 M
    m_cvt<<<(KD * KD / 4) / 256, 256>>>();

    // 5) Y = (xq @ M)/64   [8192 x 512] fp16 — fp16-accum probe (MODE 3)
    hgemm<3><<<dim3(MQ_ / BM, KD / BN, 1), 256, SMEM_ALL>>>(
        (const __half*)xq16, (const __half*)M, (__half*)Y, nullptr, nullptr,
        nullptr, 0.015625f, MQ_, KD, KD, KD / BK);

    // 6) logits = Y @ xk^T + u[t] + v[s], masked   [4,2048,4096] fp32
    hgemm<1><<<dim3(T_ / BM, S_ / BN, B_), 256, SMEM_ALL>>>(
        (const __half*)Y, (const __half*)xk16, nullptr, (float*)d_out, nullptr,
        mask, 1.0f, T_, S_, S_, KD / BK);
}

// round 7
// speedup vs baseline: 1.0443x; 1.0443x over previous
#include <cuda_runtime.h>
#include <cuda_fp16.h>
#include <cstdint>

// ---------------- fixed problem sizes ----------------
#define B_   4
#define T_   2048
#define S_   4096
#define KD   512
#define MQ_  (B_*T_)    // 8192
#define MK_  (B_*S_)    // 16384

// ---------------- GEMM tiling ----------------
#define BM 128
#define BN 128
#define BK 64
#define STAGE_BYTES (BM*128 + BN*128)       // 32 KB
#define SMEM_MAIN   (2*STAGE_BYTES)         // 64 KB
#define SMEM_EXTRA  640
#define SMEM_ALL    (SMEM_MAIN + SMEM_EXTRA)

#define MSPLIT 4
#define CONV_BLOCKS ((MQ_ + MK_) / 8)       // 3072
#define MCVT_BLOCKS ((KD * KD / 4) / 256)   // 256

// ---------------- scratch ----------------
__device__ __half g_xq16[MQ_ * KD];
__device__ __half g_xk16[MK_ * KD];
__device__ __half g_wqT[KD * KD];
__device__ __half g_wkT[KD * KD];
__device__ float  g_Mf[MSPLIT * KD * KD];
__device__ __half g_M  [KD * KD];
__device__ __half g_Y  [MQ_ * KD];
__device__ float  g_u  [MQ_];
__device__ float  g_v  [MK_];
__device__ float  g_wu [KD];
__device__ float  g_wv [KD];
__device__ float  g_c;

// ---------------- helpers ----------------
#define SWZ(o) ((o) ^ (((o) >> 3) & 0x70))

__device__ __forceinline__ uint32_t smem_u32(const void* p) {
    uint32_t a;
    asm("{ .reg .u64 t; cvta.to.shared.u64 t, %1; cvt.u32.u64 %0, t; }"
        : "=r"(a) : "l"(p));
    return a;
}

__device__ __forceinline__ void cp16(uint32_t s, const void* g) {
    asm volatile("cp.async.cg.shared.global [%0], [%1], 16;" :: "r"(s), "l"(g));
}
#define CP_COMMIT() asm volatile("cp.async.commit_group;" ::: "memory")
#define CP_WAIT0()  asm volatile("cp.async.wait_group 0;" ::: "memory")
#define CP_WAIT1()  asm volatile("cp.async.wait_group 1;" ::: "memory")

__device__ __forceinline__ void ldsm4(uint32_t* r, uint32_t addr) {
    asm volatile("ldmatrix.sync.aligned.m8n8.x4.shared.b16 {%0,%1,%2,%3}, [%4];"
                 : "=r"(r[0]), "=r"(r[1]), "=r"(r[2]), "=r"(r[3]) : "r"(addr));
}

__device__ __forceinline__ void mma16816(float* c, const uint32_t* a,
                                         uint32_t b0, uint32_t b1) {
    asm volatile(
        "mma.sync.aligned.m16n8k16.row.col.f32.f16.f16.f32 "
        "{%0,%1,%2,%3}, {%4,%5,%6,%7}, {%8,%9}, {%0,%1,%2,%3};"
        : "+f"(c[0]), "+f"(c[1]), "+f"(c[2]), "+f"(c[3])
        : "r"(a[0]), "r"(a[1]), "r"(a[2]), "r"(a[3]), "r"(b0), "r"(b1));
}

// ---------------- prep: weight transpose+cvt, wu, wv, c ----------------
__global__ void prep_small(const float* __restrict__ Wq, const float* __restrict__ Wk,
                           const float* __restrict__ bq, const float* __restrict__ bk) {
    const int b = blockIdx.x;
    if (b < 512) {
        __shared__ float tile[32][33];
        const int w = b >> 8;
        const int t = b & 255;
        const float* src = w ? Wk : Wq;
        __half* dst = w ? g_wkT : g_wqT;
        const int d0 = (t & 15) * 32, j0 = (t >> 4) * 32;
        const int tx = threadIdx.x & 31, ty = threadIdx.x >> 5;
#pragma unroll
        for (int i = 0; i < 4; ++i) {
            int j = ty + i * 8;
            tile[j][tx] = src[(size_t)(j0 + j) * KD + d0 + tx];
        }
        __syncthreads();
#pragma unroll
        for (int i = 0; i < 4; ++i) {
            int d = ty + i * 8;
            dst[(size_t)(d0 + d) * KD + j0 + tx] = __float2half(tile[tx][d]);
        }
    } else if (b < 516) {
        const int which = b - 512;
        const int d = (which & 1) * 256 + threadIdx.x;
        const float* W = (which < 2) ? Wq : Wk;
        const float* bb = (which < 2) ? bk : bq;
        float* dst = (which < 2) ? g_wu : g_wv;
        float s = 0.f;
#pragma unroll 8
        for (int j = 0; j < KD; ++j) s += bb[j] * W[(size_t)j * KD + d];
        dst[d] = s;
    } else {
        __shared__ float red[256];
        float s = bq[threadIdx.x] * bk[threadIdx.x] +
                  bq[threadIdx.x + 256] * bk[threadIdx.x + 256];
        red[threadIdx.x] = s;
        __syncthreads();
        for (int o = 128; o; o >>= 1) {
            if (threadIdx.x < (unsigned)o) red[threadIdx.x] += red[threadIdx.x + o];
            __syncthreads();
        }
        if (threadIdx.x == 0) g_c = red[0];
    }
}

// ---------- fused: fp32->fp16 convert + row GEMV (u, v)  AND  M reduce ----
// blocks [0, CONV_BLOCKS): conv+gemv (8 rows per block, 1 warp per row)
// blocks [CONV_BLOCKS, CONV_BLOCKS+MCVT_BLOCKS): sum M partials -> fp16 M
__global__ void conv_fused(const float4* __restrict__ xq,
                           const float4* __restrict__ xk) {
    if (blockIdx.x >= CONV_BLOCKS) {
        const int i = (blockIdx.x - CONV_BLOCKS) * blockDim.x + threadIdx.x;
        float4 s = *(const float4*)(g_Mf + (size_t)i * 4);
#pragma unroll
        for (int z = 1; z < MSPLIT; ++z) {
            float4 p =
                *(const float4*)(g_Mf + (size_t)z * (KD * KD) + (size_t)i * 4);
            s.x += p.x; s.y += p.y; s.z += p.z; s.w += p.w;
        }
        __half2* d = (__half2*)(g_M + (size_t)i * 4);
        d[0] = __floats2half2_rn(s.x, s.y);
        d[1] = __floats2half2_rn(s.z, s.w);
        return;
    }
    const int gw = (blockIdx.x * blockDim.x + threadIdx.x) >> 5;
    const int l = threadIdx.x & 31;
    const bool isQ = gw < MQ_;
    const int r = isQ ? gw : gw - MQ_;
    const float4* src = isQ ? xq : xk;
    const float4* w4 = (const float4*)(isQ ? g_wu : g_wv);
    __half2* dst = (__half2*)(isQ ? g_xq16 : g_xk16);
    float dot = 0.f;
#pragma unroll
    for (int i = 0; i < 4; ++i) {
        const int idx = r * (KD / 4) + l + i * 32;
        float4 a = src[idx];
        float4 w = w4[l + i * 32];
        dst[idx * 2 + 0] = __floats2half2_rn(a.x, a.y);
        dst[idx * 2 + 1] = __floats2half2_rn(a.z, a.w);
        dot += a.x * w.x + a.y * w.y + a.z * w.z + a.w * w.w;
    }
#pragma unroll
    for (int o = 16; o; o >>= 1) dot += __shfl_xor_sync(0xffffffff, dot, o);
    if (l == 0) {
        if (isQ) g_u[r] = (dot + g_c) * 0.015625f;
        else     g_v[r] = dot * 0.015625f;
    }
}

// ---------------- fp16 GEMM:  D[m,n] = sum_k A[m,k] * B[n,k]  ----------------
// MODE 0: outH = D * scale (fp16), fp32 accum
// MODE 1: outF = D + u[row] + v[col], mask -> -inf, fp32, streaming stores
// MODE 2: split-K slice -> fp32 partials
template <int MODE>
__global__ __launch_bounds__(256, 2) void hgemm(
    const __half* __restrict__ A, const __half* __restrict__ Bm,
    __half* __restrict__ outH, float* __restrict__ outF,
    float* __restrict__ outMf, const unsigned char* __restrict__ mask,
    float scale, int aRows, int bRows, int outLd, int nch) {
    extern __shared__ char smem[];
    const uint32_t sb = smem_u32(smem);
    const int tid = threadIdx.x;
    const int wid = tid >> 5;
    const int l = tid & 31;
    const int wm = wid >> 2;
    const int wn = wid & 3;
    const int mt = blockIdx.x, nt = blockIdx.y, bz = blockIdx.z;

    size_t aBase, bBase;
    int kStart;
    if (MODE == 2) {
        aBase = (size_t)mt * BM * KD;
        bBase = (size_t)nt * BN * KD;
        kStart = bz * (KD / MSPLIT);
    } else {
        aBase = ((size_t)bz * aRows + (size_t)mt * BM) * KD;
        bBase = ((size_t)bz * bRows + (size_t)nt * BN) * KD;
        kStart = 0;
    }

    float* sv = (float*)(smem + SMEM_MAIN);
    unsigned char* sm = (unsigned char*)(smem + SMEM_MAIN + 512);
    if (MODE == 1 && tid < 128) {
        const size_t colg = (size_t)bz * S_ + (size_t)nt * BN + tid;
        sv[tid] = g_v[colg];
        sm[tid] = mask[colg];
    }

    float acc[4][4][4];
#pragma unroll
    for (int i = 0; i < 4; ++i)
#pragma unroll
        for (int j = 0; j < 4; ++j)
#pragma unroll
            for (int c = 0; c < 4; ++c) acc[i][j][c] = 0.f;

    const int aRow = wm * 64 + (l & 15);
    const int aKsel = ((l >> 4) & 1) * 16;
    const int bRow = wn * 32 + (l & 7) + ((l >> 4) & 1) * 8;
    const int bKsel = ((l >> 3) & 1) * 16;

    auto load_tile = [&](int stg, int k0) {
        const uint32_t sA = sb + stg * STAGE_BYTES;
        const uint32_t sB = sA + BM * 128;
#pragma unroll
        for (int t = 0; t < 4; ++t) {
            int i = tid + t * 256;
            int r = i >> 3, c = i & 7;
            cp16(sA + SWZ((uint32_t)(r * 128 + c * 16)),
                 A + aBase + (size_t)r * KD + k0 + c * 8);
        }
#pragma unroll
        for (int t = 0; t < 4; ++t) {
            int i = tid + t * 256;
            int r = i >> 3, c = i & 7;
            cp16(sB + SWZ((uint32_t)(r * 128 + c * 16)),
                 Bm + bBase + (size_t)r * KD + k0 + c * 8);
        }
    };

    load_tile(0, kStart);
    CP_COMMIT();

    int stg = 0;
    for (int ch = 0; ch < nch; ++ch) {
        if (ch + 1 < nch) {
            load_tile(stg ^ 1, kStart + (ch + 1) * BK);
            CP_COMMIT();
            CP_WAIT1();
        } else {
            CP_WAIT0();
        }
        __syncthreads();

        const uint32_t sA = sb + stg * STAGE_BYTES;
        const uint32_t sB = sA + BM * 128;
#pragma unroll
        for (int ks = 0; ks < BK / 16; ++ks) {
            uint32_t afr[4][4];
            uint32_t bfr[2][4];
#pragma unroll
            for (int mi = 0; mi < 4; ++mi)
                ldsm4(afr[mi], sA + SWZ((uint32_t)((aRow + mi * 16) * 128 +
                                                   ks * 32 + aKsel)));
#pragma unroll
            for (int nb = 0; nb < 2; ++nb)
                ldsm4(bfr[nb], sB + SWZ((uint32_t)((bRow + nb * 16) * 128 +
                                                   ks * 32 + bKsel)));
#pragma unroll
            for (int mi = 0; mi < 4; ++mi)
#pragma unroll
                for (int ni = 0; ni < 4; ++ni)
                    mma16816(acc[mi][ni], afr[mi], bfr[ni >> 1][(ni & 1) * 2],
                             bfr[ni >> 1][(ni & 1) * 2 + 1]);
        }
        __syncthreads();
        stg ^= 1;
    }

    // ---------------- epilogue ----------------
    const int gid = l >> 2, tig = l & 3;
#pragma unroll
    for (int mi = 0; mi < 4; ++mi) {
#pragma unroll
        for (int h = 0; h < 2; ++h) {
            const int row = mt * BM + wm * 64 + mi * 16 + gid + h * 8;
            const size_t rowg =
                (MODE == 2) ? (size_t)row : (size_t)bz * aRows + row;
            float uu = 0.f;
            if (MODE == 1) uu = g_u[rowg];
#pragma unroll
            for (int ni = 0; ni < 4; ++ni) {
                const int lcol = wn * 32 + ni * 8 + tig * 2;
                const int col = nt * BN + lcol;
                const float v0 = acc[mi][ni][h * 2 + 0];
                const float v1 = acc[mi][ni][h * 2 + 1];
                if (MODE == 0) {
                    *(__half2*)(outH + rowg * outLd + col) =
                        __floats2half2_rn(v0 * scale, v1 * scale);
                } else if (MODE == 2) {
                    float* dst = outMf + (size_t)bz * (KD * KD) +
                                 rowg * outLd + col;
                    dst[0] = v0;
                    dst[1] = v1;
                } else {
                    const float NEG_INF = __int_as_float(0xff800000);
                    float2 o;
                    o.x = sm[lcol + 0] ? NEG_INF : v0 + uu + sv[lcol + 0];
                    o.y = sm[lcol + 1] ? NEG_INF : v1 + uu + sv[lcol + 1];
                    __stcs((float2*)(outF + rowg * (size_t)S_ + col), o);
                }
            }
        }
    }
}

// ---------------- host launch ----------------
extern "C" void kernel_launch(void* const* d_in, const int* in_sizes, int n_in,
                              void* d_out, int out_size) {
    const float* query = (const float*)d_in[0];
    const float* keys = (const float*)d_in[1];
    const unsigned char* mask = (const unsigned char*)d_in[2];
    const float* q_w = (const float*)d_in[3];
    const float* q_b = (const float*)d_in[4];
    const float* k_w = (const float*)d_in[5];
    const float* k_b = (const float*)d_in[6];

    void *xq16, *xk16, *wqT, *wkT, *Mf, *M, *Y;
    cudaGetSymbolAddress(&xq16, g_xq16);
    cudaGetSymbolAddress(&xk16, g_xk16);
    cudaGetSymbolAddress(&wqT, g_wqT);
    cudaGetSymbolAddress(&wkT, g_wkT);
    cudaGetSymbolAddress(&Mf, g_Mf);
    cudaGetSymbolAddress(&M, g_M);
    cudaGetSymbolAddress(&Y, g_Y);

    cudaFuncSetAttribute(hgemm<0>, cudaFuncAttributeMaxDynamicSharedMemorySize,
                         SMEM_ALL);
    cudaFuncSetAttribute(hgemm<1>, cudaFuncAttributeMaxDynamicSharedMemorySize,
                         SMEM_ALL);
    cudaFuncSetAttribute(hgemm<2>, cudaFuncAttributeMaxDynamicSharedMemorySize,
                         SMEM_ALL);

    // 1) weight transpose/convert + wu, wv, c
    prep_small<<<517, 256>>>(q_w, k_w, q_b, k_b);

    // 2) M partials: split-K over 4 slices (K=128 each)
    hgemm<2><<<dim3(KD / BM, KD / BN, MSPLIT), 256, SMEM_ALL>>>(
        (const __half*)wkT, (const __half*)wqT, nullptr, nullptr, (float*)Mf,
        nullptr, 1.0f, KD, KD, KD, (KD / MSPLIT) / BK);

    // 3) fused: convert xq/xk + row GEMVs u,v  +  M partial reduce -> fp16
    conv_fused<<<CONV_BLOCKS + MCVT_BLOCKS, 256>>>((const float4*)query,
                                                   (const float4*)keys);

    // 4) Y = (xq @ M)/64   [8192 x 512] fp16, fp32 accum
    hgemm<0><<<dim3(MQ_ / BM, KD / BN, 1), 256, SMEM_ALL>>>(
        (const __half*)xq16, (const __half*)M, (__half*)Y, nullptr, nullptr,
        nullptr, 0.015625f, MQ_, KD, KD, KD / BK);

    // 5) logits = Y @ xk^T + u[t] + v[s], masked   [4,2048,4096] fp32
    hgemm<1><<<dim3(T_ / BM, S_ / BN, B_), 256, SMEM_ALL>>>(
        (const __half*)Y, (const __half*)xk16, nullptr, (float*)d_out, nullptr,
        mask, 1.0f, T_, S_, S_, KD / BK);
}